// round 13
// baseline (speedup 1.0000x reference)
#include <cuda_runtime.h>
#include <cuda_bf16.h>
#include <stdint.h>
#include <math.h>

#define B_  4
#define S_  2048
#define D_  1024
#define MS  (B_*S_)
#define BK  16
#define NSTG 4
#define OFF_AL 4096
#define OFF_BH 8192
#define OFF_BL 16384
#define CHUNK_B 24576                  // one k16 chunk image: [Ah 4K][Al 4K][Bh 8K][Bl 8K]
#define SLOT_B (2*CHUNK_B)             // 48 KB: two consecutive k16 chunks
#define SMEM_DYN (NSTG*SLOT_B)         // 192 KB
#define NTHREADS 288                   // 8 consumer warps + 1 producer warp

typedef __nv_bfloat16 bf16;

// ---------------------------------------------------------------------------
// Packed operand layout ("stage image"): [blk128][kchunk][swizzled 128x16]
// ---------------------------------------------------------------------------
__host__ __device__ __forceinline__ size_t pk_off(int r, int k, int KCtot) {
    const int u = (r & 127) * 2 + (((k >> 3) & 1) ^ ((r >> 2) & 1));
    return ((size_t)((r >> 7) * KCtot + (k >> 4)) * 2048) + (size_t)u * 8 + (k & 7);
}

__device__ __forceinline__ uint32_t swzb(int row, int chunk) {
    return (uint32_t)((row * 2 + (chunk ^ ((row >> 2) & 1))) * 16);
}

// ---------------------------------------------------------------------------
// Device-global scratch
// ---------------------------------------------------------------------------
__device__ bf16 g_xh[MS * D_], g_xl[MS * D_];                // packed, KCtot=64
__device__ bf16 g_Wth[3][D_ * D_], g_Wtl[3][D_ * D_];        // packed W^T, KCtot=64
__device__ bf16 g_Qh[MS * D_], g_Ql[MS * D_];                // packed, KCtot=64
__device__ bf16 g_Kh[MS * D_], g_Kl[MS * D_];                // packed, KCtot=64
__device__ bf16 g_Vh[MS * D_], g_Vl[MS * D_];                // PLAIN row-major [m][d]
__device__ bf16 g_Vth[MS * D_], g_Vtl[MS * D_];              // packed V^T, KCtot=128
__device__ float g_S[(size_t)B_ * S_ * S_];                  // plain fp32
__device__ bf16 g_Ph[(size_t)B_ * S_ * S_], g_Pl[(size_t)B_ * S_ * S_]; // packed, KCtot=128

// ---------------------------------------------------------------------------
// Helpers
// ---------------------------------------------------------------------------
__device__ __forceinline__ void split1(float v, bf16& h, bf16& l) {
    h = __float2bfloat16_rn(v);
    l = __float2bfloat16_rn(v - __bfloat162float(h));
}

__device__ __forceinline__ void ldsm4(uint32_t r[4], uint32_t a) {
    asm volatile("ldmatrix.sync.aligned.m8n8.x4.shared.b16 {%0,%1,%2,%3}, [%4];"
                 : "=r"(r[0]), "=r"(r[1]), "=r"(r[2]), "=r"(r[3]) : "r"(a));
}

__device__ __forceinline__ void mma_bf16(float c[4], const uint32_t a[4],
                                         const uint32_t b0, const uint32_t b1) {
    asm volatile(
        "mma.sync.aligned.m16n8k16.row.col.f32.bf16.bf16.f32 "
        "{%0,%1,%2,%3},{%4,%5,%6,%7},{%8,%9},{%0,%1,%2,%3};"
        : "+f"(c[0]), "+f"(c[1]), "+f"(c[2]), "+f"(c[3])
        : "r"(a[0]), "r"(a[1]), "r"(a[2]), "r"(a[3]), "r"(b0), "r"(b1));
}

__device__ __forceinline__ void bulk4k(uint32_t dst, const void* src, uint32_t mbar) {
    asm volatile(
        "cp.async.bulk.shared::cluster.global.mbarrier::complete_tx::bytes "
        "[%0], [%1], 4096, [%2];"
        :: "r"(dst), "l"(src), "r"(mbar) : "memory");
}

__device__ __forceinline__ void mbar_wait(uint32_t mbar, uint32_t parity) {
    uint32_t done;
    asm volatile(
        "{\n\t.reg .pred p;\n\t"
        "mbarrier.try_wait.parity.acquire.cta.shared::cta.b64 p, [%1], %2;\n\t"
        "selp.b32 %0, 1, 0, p;\n\t}"
        : "=r"(done) : "r"(mbar), "r"(parity) : "memory");
    if (!done) {
        asm volatile(
            "{\n\t.reg .pred P1;\n\t"
            "WAIT_LOOP_%=:\n\t"
            "mbarrier.try_wait.parity.acquire.cta.shared::cta.b64 P1, [%0], %1, 0x989680;\n\t"
            "@P1 bra.uni WAIT_DONE_%=;\n\t"
            "bra.uni WAIT_LOOP_%=;\n\t"
            "WAIT_DONE_%=:\n\t}"
            :: "r"(mbar), "r"(parity) : "memory");
    }
}

// ---------------------------------------------------------------------------
// Slot issue: one thread, 12 x 4KB bulk copies (two k16 chunks) per slot
// ---------------------------------------------------------------------------
__device__ __forceinline__ void issue_slot(uint32_t slot, uint32_t mbar,
        const bf16* __restrict__ Ah, const bf16* __restrict__ Al,
        const bf16* __restrict__ Bh, const bf16* __restrict__ Bl,
        int mblk, int nblk0, int stage, int KCA, int KCB) {
    asm volatile("mbarrier.arrive.expect_tx.shared.b64 _, [%0], %1;"
                 :: "r"(mbar), "r"(49152u) : "memory");
#pragma unroll
    for (int c = 0; c < 2; c++) {
        const uint32_t st = slot + c * CHUNK_B;
        const int kc = 2 * stage + c;
        const size_t ao = ((size_t)mblk * KCA + kc) * 2048;
        bulk4k(st,              Ah + ao, mbar);
        bulk4k(st + OFF_AL,     Al + ao, mbar);
        const size_t b0 = ((size_t)nblk0 * KCB + kc) * 2048;
        const size_t b1 = ((size_t)(nblk0 + 1) * KCB + kc) * 2048;
        bulk4k(st + OFF_BH,        Bh + b0, mbar);
        bulk4k(st + OFF_BH + 4096, Bh + b1, mbar);
        bulk4k(st + OFF_BL,        Bl + b0, mbar);
        bulk4k(st + OFF_BL + 4096, Bl + b1, mbar);
    }
}

// ---------------------------------------------------------------------------
// Fragment bundle (reused across sub-chunks — no register doubling)
// ---------------------------------------------------------------------------
struct Frags { uint32_t ah[4][4], al[4][4], bh[4][4], bl[4][4]; };

__device__ __forceinline__ void load_frags(Frags& f, uint32_t st,
        int wm, int bblk, int bri, int arow, int achk, int brow, int bchk) {
#pragma unroll
    for (int i = 0; i < 4; i++) {
        const uint32_t o = swzb(wm + 16 * i + arow, achk);
        ldsm4(f.ah[i], st + o);
        ldsm4(f.al[i], st + OFF_AL + o);
    }
#pragma unroll
    for (int p = 0; p < 4; p++) {
        const uint32_t o = bblk * 4096 + swzb(bri + 16 * p + brow, bchk);
        ldsm4(f.bh[p], st + OFF_BH + o);
        ldsm4(f.bl[p], st + OFF_BL + o);
    }
}

__device__ __forceinline__ void mma_frags(const Frags& f, float acc[4][8][4]) {
    // term 0: Ah*Bh
#pragma unroll
    for (int i = 0; i < 4; i++)
#pragma unroll
        for (int jj = 0; jj < 8; jj++) {
            const int p = jj >> 1, q = (jj & 1) * 2;
            mma_bf16(acc[i][jj], f.ah[i], f.bh[p][q], f.bh[p][q + 1]);
        }
    // term 1: Al*Bh
#pragma unroll
    for (int i = 0; i < 4; i++)
#pragma unroll
        for (int jj = 0; jj < 8; jj++) {
            const int p = jj >> 1, q = (jj & 1) * 2;
            mma_bf16(acc[i][jj], f.al[i], f.bh[p][q], f.bh[p][q + 1]);
        }
    // term 2: Ah*Bl
#pragma unroll
    for (int i = 0; i < 4; i++)
#pragma unroll
        for (int jj = 0; jj < 8; jj++) {
            const int p = jj >> 1, q = (jj & 1) * 2;
            mma_bf16(acc[i][jj], f.ah[i], f.bl[p][q], f.bl[p][q + 1]);
        }
}

// ---------------------------------------------------------------------------
// GEMM mainloop: C 128x256 block from packed operands. WARP-SPECIALIZED:
// warp 8 = dedicated producer (lane 0 issues all slot DMAs, paced by empty
// barriers); warps 0-7 = consumers (wait full -> ldsm/MMA x2 -> arrive empty)
// with NO intra-loop bar.sync and no producer duties — free to skew across
// the 4-deep pipeline. Chunk->slot: stage t in slot (t&3). Parities:
// full[s] waited at stage t with (t>>2)&1 (fill #k=t/4); empty[s] waited by
// producer before fill k>=1 with (k-1)&1 (release #k-1). MMA-before-arrive
// guarantees the warp's LDSM smem reads retired before refill can clobber.
// ---------------------------------------------------------------------------
__device__ void gemm_core(
    const bf16* __restrict__ Ahp, const bf16* __restrict__ Alp,
    const bf16* __restrict__ Bhp, const bf16* __restrict__ Blp,
    int mblk, int nblk0, int KC, int KCA, int KCB, float acc[4][8][4])
{
    extern __shared__ char dsm[];
    __shared__ uint64_t mbars[NSTG];    // full barriers (tx-count, 1 arrival)
    __shared__ uint64_t embars[NSTG];   // empty barriers (8 warp arrivals)
    const uint32_t sb = (uint32_t)__cvta_generic_to_shared(dsm);
    const uint32_t mb0 = (uint32_t)__cvta_generic_to_shared(mbars);
    const uint32_t eb0 = (uint32_t)__cvta_generic_to_shared(embars);

    const int tid = threadIdx.x, lane = tid & 31, warp = tid >> 5;

    const int KC2 = KC / 2;            // stages

    if (tid == 0) {
#pragma unroll
        for (int s = 0; s < NSTG; s++) {
            asm volatile("mbarrier.init.shared.b64 [%0], %1;"
                         :: "r"(mb0 + 8 * s), "r"(1u) : "memory");
            asm volatile("mbarrier.init.shared.b64 [%0], %1;"
                         :: "r"(eb0 + 8 * s), "r"(8u) : "memory");
        }
    }
    __syncthreads();                   // all 289... all 288 threads

    if (warp == 8) {
        // ------------------ producer warp ------------------
        if (lane == 0) {
            for (int t = 0; t < KC2; t++) {
                const int s = t & 3, k = t >> 2;
                if (t >= NSTG)
                    mbar_wait(eb0 + 8 * s, (uint32_t)((k - 1) & 1));
                issue_slot(sb + s * SLOT_B, mb0 + 8 * s,
                           Ahp, Alp, Bhp, Blp, mblk, nblk0, t, KCA, KCB);
            }
        }
        return;
    }

    // -------------------- consumer warps 0..7 --------------------
    const int wm = (warp >> 2) * 64, wn = (warp & 3) * 64;
    const int arow = (lane & 7) + 8 * ((lane >> 3) & 1);
    const int achk = lane >> 4;
    const int brow = (lane & 7) + 8 * ((lane >> 4) & 1);
    const int bchk = (lane >> 3) & 1;
    const int bblk = wn >> 7;
    const int bri = (wn & 127);

    Frags f;
    for (int t = 0; t < KC2; t++) {
        const int s = t & 3;
        mbar_wait(mb0 + 8 * s, (uint32_t)((t >> 2) & 1));

        const uint32_t slot = sb + s * SLOT_B;

        load_frags(f, slot, wm, bblk, bri, arow, achk, brow, bchk);
        mma_frags(f, acc);

        load_frags(f, slot + CHUNK_B, wm, bblk, bri, arow, achk, brow, bchk);
        mma_frags(f, acc);

        if (lane == 0)
            asm volatile("mbarrier.arrive.shared.b64 _, [%0];"
                         :: "r"(eb0 + 8 * s) : "memory");
    }
}

// ---------------------------------------------------------------------------
// Conversion kernels
// ---------------------------------------------------------------------------
__global__ void convert_x_kernel(const float* __restrict__ x) {
    size_t i = ((size_t)blockIdx.x * 256 + threadIdx.x) * 4;
    const int m = (int)(i / D_), k = (int)(i % D_);
    float4 v = *(const float4*)(x + i);
    bf16 h0, l0, h1, l1, h2, l2, h3, l3;
    split1(v.x, h0, l0); split1(v.y, h1, l1);
    split1(v.z, h2, l2); split1(v.w, h3, l3);
    const size_t o = pk_off(m, k, D_ / 16);
    *(__nv_bfloat162*)(g_xh + o)     = __halves2bfloat162(h0, h1);
    *(__nv_bfloat162*)(g_xh + o + 2) = __halves2bfloat162(h2, h3);
    *(__nv_bfloat162*)(g_xl + o)     = __halves2bfloat162(l0, l1);
    *(__nv_bfloat162*)(g_xl + o + 2) = __halves2bfloat162(l2, l3);
}

__global__ void convert_Wt_kernel(const float* __restrict__ Wq,
                                  const float* __restrict__ Wk,
                                  const float* __restrict__ Wv) {
    const float* W = blockIdx.z == 0 ? Wq : blockIdx.z == 1 ? Wk : Wv;
    bf16* Oh = g_Wth[blockIdx.z];
    bf16* Ol = g_Wtl[blockIdx.z];
    __shared__ float t[32][33];
    const int k0 = blockIdx.y * 32, n0 = blockIdx.x * 32;
    const int tx = threadIdx.x, ty = threadIdx.y;
#pragma unroll
    for (int r = 0; r < 32; r += 8)
        t[ty + r][tx] = W[(size_t)(k0 + ty + r) * D_ + n0 + tx];
    __syncthreads();
#pragma unroll
    for (int r = 0; r < 32; r += 8) {
        float v = t[tx][ty + r];
        bf16 h, l; split1(v, h, l);
        const size_t o = pk_off(n0 + ty + r, k0 + tx, D_ / 16);
        Oh[o] = h; Ol[o] = l;
    }
}

__global__ void transpose_V_kernel() {
    __shared__ bf16 th[32][33], tl[32][33];
    const int b = blockIdx.z;
    const int t0 = blockIdx.x * 32, d0 = blockIdx.y * 32;
    const int tx = threadIdx.x, ty = threadIdx.y;
    const bf16* Vh = g_Vh + (size_t)b * S_ * D_;
    const bf16* Vl = g_Vl + (size_t)b * S_ * D_;
#pragma unroll
    for (int r = 0; r < 32; r += 8) {
        size_t o = (size_t)(t0 + ty + r) * D_ + d0 + tx;
        th[ty + r][tx] = Vh[o];
        tl[ty + r][tx] = Vl[o];
    }
    __syncthreads();
#pragma unroll
    for (int r = 0; r < 32; r += 8) {
        const size_t o = pk_off(b * D_ + d0 + ty + r, t0 + tx, S_ / 16);
        g_Vth[o] = th[tx][ty + r];
        g_Vtl[o] = tl[tx][ty + r];
    }
}

// ---------------------------------------------------------------------------
// GEMM 1: QKV projection. Q,K written packed; V written plain row-major.
// ---------------------------------------------------------------------------
__global__ __launch_bounds__(NTHREADS, 1) void gemm_proj_kernel(
    const float* __restrict__ bqp, const float* __restrict__ bkp,
    const float* __restrict__ bvp) {
    const int z = blockIdx.z;
    const float* bias = z == 0 ? bqp : z == 1 ? bkp : bvp;
    const int bm = blockIdx.y * 128, bn = blockIdx.x * 256;

    float acc[4][8][4] = {};
    gemm_core(g_xh, g_xl, g_Wth[z], g_Wtl[z],
              blockIdx.y, blockIdx.x * 2, D_ / BK, D_ / 16, D_ / 16, acc);

    const int lane = threadIdx.x & 31, warp = threadIdx.x >> 5;
    if (warp >= 8) return;
    const int wm = (warp >> 2) * 64, wn = (warp & 3) * 64;
    const int g = lane >> 2, t = lane & 3;
#pragma unroll
    for (int i = 0; i < 4; i++)
#pragma unroll
        for (int j = 0; j < 8; j++) {
            const int col = bn + wn + 8 * j + 2 * t;
            const float b0 = bias[col], b1 = bias[col + 1];
#pragma unroll
            for (int h2 = 0; h2 < 2; h2++) {
                const int r0 = bm + wm + 16 * i + g + 8 * h2;
                bf16 h0, l0, h1, l1;
                split1(acc[i][j][2 * h2 + 0] + b0, h0, l0);
                split1(acc[i][j][2 * h2 + 1] + b1, h1, l1);
                if (z < 2) {
                    bf16* Ch = z == 0 ? g_Qh : g_Kh;
                    bf16* Cl = z == 0 ? g_Ql : g_Kl;
                    const size_t o = pk_off(r0, col, D_ / 16);
                    *(__nv_bfloat162*)(Ch + o) = __halves2bfloat162(h0, h1);
                    *(__nv_bfloat162*)(Cl + o) = __halves2bfloat162(l0, l1);
                } else {
                    const size_t o = (size_t)r0 * D_ + col;
                    *(__nv_bfloat162*)(g_Vh + o) = __halves2bfloat162(h0, h1);
                    *(__nv_bfloat162*)(g_Vl + o) = __halves2bfloat162(l0, l1);
                }
            }
        }
}

// ---------------------------------------------------------------------------
// GEMM 2: scores = (Q @ K^T) * scale  (fp32 plain out)
// ---------------------------------------------------------------------------
__global__ __launch_bounds__(NTHREADS, 1) void gemm_scores_kernel() {
    const int b = blockIdx.z;
    const int bm = blockIdx.y * 128, bn = blockIdx.x * 256;

    float acc[4][8][4] = {};
    gemm_core(g_Qh, g_Ql, g_Kh, g_Kl,
              b * 16 + blockIdx.y, b * 16 + blockIdx.x * 2,
              D_ / BK, D_ / 16, D_ / 16, acc);

    float* C = g_S + (size_t)b * S_ * S_;
    const int lane = threadIdx.x & 31, warp = threadIdx.x >> 5;
    if (warp >= 8) return;
    const int wm = (warp >> 2) * 64, wn = (warp & 3) * 64;
    const int g = lane >> 2, t = lane & 3;
    const float sc = 0.03125f;
#pragma unroll
    for (int i = 0; i < 4; i++)
#pragma unroll
        for (int j = 0; j < 8; j++) {
            const int col = bn + wn + 8 * j + 2 * t;
            const int r0 = bm + wm + 16 * i + g;
            *(float2*)(C + (size_t)r0 * S_ + col) =
                make_float2(acc[i][j][0] * sc, acc[i][j][1] * sc);
            *(float2*)(C + (size_t)(r0 + 8) * S_ + col) =
                make_float2(acc[i][j][2] * sc, acc[i][j][3] * sc);
        }
}

// ---------------------------------------------------------------------------
// Softmax: fp32 scores -> packed attn bf16 hi/lo
// ---------------------------------------------------------------------------
__global__ __launch_bounds__(256) void softmax_kernel() {
    const int row = blockIdx.x;
    const float* p = g_S + (size_t)row * S_;
    const int tid = threadIdx.x;

    __shared__ float red[256];

    float v[8];
    float m = -INFINITY;
#pragma unroll
    for (int i = 0; i < 8; i++) {
        v[i] = p[tid + i * 256];
        m = fmaxf(m, v[i]);
    }
    red[tid] = m;
    __syncthreads();
    for (int s = 128; s > 0; s >>= 1) {
        if (tid < s) red[tid] = fmaxf(red[tid], red[tid + s]);
        __syncthreads();
    }
    m = red[0];
    __syncthreads();

    float sum = 0.f;
#pragma unroll
    for (int i = 0; i < 8; i++) {
        v[i] = __expf(v[i] - m);
        sum += v[i];
    }
    red[tid] = sum;
    __syncthreads();
    for (int s = 128; s > 0; s >>= 1) {
        if (tid < s) red[tid] += red[tid + s];
        __syncthreads();
    }
    const float inv = 1.0f / red[0];
#pragma unroll
    for (int i = 0; i < 8; i++) {
        bf16 h, l;
        split1(v[i] * inv, h, l);
        const size_t o = pk_off(row, tid + i * 256, S_ / 16);
        g_Ph[o] = h;
        g_Pl[o] = l;
    }
}

// ---------------------------------------------------------------------------
// GEMM 3: out = attn @ V  (fp32 plain out)
// ---------------------------------------------------------------------------
__global__ __launch_bounds__(NTHREADS, 1) void gemm_av_kernel(float* __restrict__ out) {
    const int b = blockIdx.z;
    const int bm = blockIdx.y * 128, bn = blockIdx.x * 256;

    float acc[4][8][4] = {};
    gemm_core(g_Ph, g_Pl, g_Vth, g_Vtl,
              b * 16 + blockIdx.y, b * 8 + blockIdx.x * 2,
              S_ / BK, S_ / 16, S_ / 16, acc);

    float* C = out + (size_t)b * S_ * D_;
    const int lane = threadIdx.x & 31, warp = threadIdx.x >> 5;
    if (warp >= 8) return;
    const int wm = (warp >> 2) * 64, wn = (warp & 3) * 64;
    const int g = lane >> 2, t = lane & 3;
#pragma unroll
    for (int i = 0; i < 4; i++)
#pragma unroll
        for (int j = 0; j < 8; j++) {
            const int col = bn + wn + 8 * j + 2 * t;
            const int r0 = bm + wm + 16 * i + g;
            *(float2*)(C + (size_t)r0 * D_ + col) =
                make_float2(acc[i][j][0], acc[i][j][1]);
            *(float2*)(C + (size_t)(r0 + 8) * D_ + col) =
                make_float2(acc[i][j][2], acc[i][j][3]);
        }
}

// ---------------------------------------------------------------------------
// Launch
// ---------------------------------------------------------------------------
extern "C" void kernel_launch(void* const* d_in, const int* in_sizes, int n_in,
                              void* d_out, int out_size) {
    const float* x  = (const float*)d_in[0];
    const float* Wq = (const float*)d_in[1];
    const float* bq = (const float*)d_in[2];
    const float* Wk = (const float*)d_in[3];
    const float* bk = (const float*)d_in[4];
    const float* Wv = (const float*)d_in[5];
    const float* bv = (const float*)d_in[6];
    float* out = (float*)d_out;

    cudaFuncSetAttribute(gemm_proj_kernel,
                         cudaFuncAttributeMaxDynamicSharedMemorySize, SMEM_DYN);
    cudaFuncSetAttribute(gemm_scores_kernel,
                         cudaFuncAttributeMaxDynamicSharedMemorySize, SMEM_DYN);
    cudaFuncSetAttribute(gemm_av_kernel,
                         cudaFuncAttributeMaxDynamicSharedMemorySize, SMEM_DYN);

    convert_x_kernel<<<(MS * D_) / 1024, 256>>>(x);
    convert_Wt_kernel<<<dim3(32, 32, 3), dim3(32, 8)>>>(Wq, Wk, Wv);

    gemm_proj_kernel<<<dim3(D_ / 256, MS / 128, 3), NTHREADS, SMEM_DYN>>>(bq, bk, bv);

    gemm_scores_kernel<<<dim3(S_ / 256, S_ / 128, B_), NTHREADS, SMEM_DYN>>>();

    transpose_V_kernel<<<dim3(S_ / 32, D_ / 32, B_), dim3(32, 8)>>>();

    softmax_kernel<<<B_ * S_, 256>>>();

    gemm_av_kernel<<<dim3(D_ / 256, S_ / 128, B_), NTHREADS, SMEM_DYN>>>(out);
}

// round 14
// speedup vs baseline: 1.1362x; 1.1362x over previous
#include <cuda_runtime.h>
#include <cuda_bf16.h>
#include <stdint.h>
#include <math.h>

#define B_  4
#define S_  2048
#define D_  1024
#define MS  (B_*S_)
#define BK  16
#define NSTG 3
#define OFF_AL 4096
#define OFF_BH 8192
#define OFF_BL 12288
#define CHUNK_B 16384                  // k16 chunk image: [Ah 4K][Al 4K][Bh 4K][Bl 4K]
#define SLOT_B (2*CHUNK_B)             // 32 KB: two consecutive k16 chunks
#define SMEM_DYN (NSTG*SLOT_B)         // 96 KB -> 2 CTAs/SM
#define NTHREADS 128                   // 4 warps, 2(m) x 2(n), warp tile 64x64

typedef __nv_bfloat16 bf16;

// ---------------------------------------------------------------------------
// Packed operand layout ("stage image"): [blk128][kchunk][swizzled 128x16]
// ---------------------------------------------------------------------------
__host__ __device__ __forceinline__ size_t pk_off(int r, int k, int KCtot) {
    const int u = (r & 127) * 2 + (((k >> 3) & 1) ^ ((r >> 2) & 1));
    return ((size_t)((r >> 7) * KCtot + (k >> 4)) * 2048) + (size_t)u * 8 + (k & 7);
}

__device__ __forceinline__ uint32_t swzb(int row, int chunk) {
    return (uint32_t)((row * 2 + (chunk ^ ((row >> 2) & 1))) * 16);
}

// ---------------------------------------------------------------------------
// Device-global scratch
// ---------------------------------------------------------------------------
__device__ bf16 g_xh[MS * D_], g_xl[MS * D_];                // packed, KCtot=64
__device__ bf16 g_Wth[3][D_ * D_], g_Wtl[3][D_ * D_];        // packed W^T, KCtot=64
__device__ bf16 g_Qh[MS * D_], g_Ql[MS * D_];                // packed, KCtot=64
__device__ bf16 g_Kh[MS * D_], g_Kl[MS * D_];                // packed, KCtot=64
__device__ bf16 g_Vh[MS * D_], g_Vl[MS * D_];                // PLAIN row-major [m][d]
__device__ bf16 g_Vth[MS * D_], g_Vtl[MS * D_];              // packed V^T, KCtot=128
__device__ float g_S[(size_t)B_ * S_ * S_];                  // plain fp32
__device__ bf16 g_Ph[(size_t)B_ * S_ * S_], g_Pl[(size_t)B_ * S_ * S_]; // packed, KCtot=128

// ---------------------------------------------------------------------------
// Helpers
// ---------------------------------------------------------------------------
__device__ __forceinline__ void split1(float v, bf16& h, bf16& l) {
    h = __float2bfloat16_rn(v);
    l = __float2bfloat16_rn(v - __bfloat162float(h));
}

__device__ __forceinline__ void ldsm4(uint32_t r[4], uint32_t a) {
    asm volatile("ldmatrix.sync.aligned.m8n8.x4.shared.b16 {%0,%1,%2,%3}, [%4];"
                 : "=r"(r[0]), "=r"(r[1]), "=r"(r[2]), "=r"(r[3]) : "r"(a));
}

__device__ __forceinline__ void mma_bf16(float c[4], const uint32_t a[4],
                                         const uint32_t b0, const uint32_t b1) {
    asm volatile(
        "mma.sync.aligned.m16n8k16.row.col.f32.bf16.bf16.f32 "
        "{%0,%1,%2,%3},{%4,%5,%6,%7},{%8,%9},{%0,%1,%2,%3};"
        : "+f"(c[0]), "+f"(c[1]), "+f"(c[2]), "+f"(c[3])
        : "r"(a[0]), "r"(a[1]), "r"(a[2]), "r"(a[3]), "r"(b0), "r"(b1));
}

__device__ __forceinline__ void bulk4k(uint32_t dst, const void* src, uint32_t mbar) {
    asm volatile(
        "cp.async.bulk.shared::cluster.global.mbarrier::complete_tx::bytes "
        "[%0], [%1], 4096, [%2];"
        :: "r"(dst), "l"(src), "r"(mbar) : "memory");
}

__device__ __forceinline__ void mbar_wait(uint32_t mbar, uint32_t parity) {
    uint32_t done;
    asm volatile(
        "{\n\t.reg .pred p;\n\t"
        "mbarrier.try_wait.parity.acquire.cta.shared::cta.b64 p, [%1], %2;\n\t"
        "selp.b32 %0, 1, 0, p;\n\t}"
        : "=r"(done) : "r"(mbar), "r"(parity) : "memory");
    if (!done) {
        asm volatile(
            "{\n\t.reg .pred P1;\n\t"
            "WAIT_LOOP_%=:\n\t"
            "mbarrier.try_wait.parity.acquire.cta.shared::cta.b64 P1, [%0], %1, 0x989680;\n\t"
            "@P1 bra.uni WAIT_DONE_%=;\n\t"
            "bra.uni WAIT_LOOP_%=;\n\t"
            "WAIT_DONE_%=:\n\t}"
            :: "r"(mbar), "r"(parity) : "memory");
    }
}

// ---------------------------------------------------------------------------
// Slot issue: one thread, 8 x 4KB bulk copies (two k16 chunks) per slot
// ---------------------------------------------------------------------------
__device__ __forceinline__ void issue_slot(uint32_t slot, uint32_t mbar,
        const bf16* __restrict__ Ah, const bf16* __restrict__ Al,
        const bf16* __restrict__ Bh, const bf16* __restrict__ Bl,
        int mblk, int nblk, int stage, int KCA, int KCB) {
    asm volatile("mbarrier.arrive.expect_tx.shared.b64 _, [%0], %1;"
                 :: "r"(mbar), "r"(32768u) : "memory");
#pragma unroll
    for (int c = 0; c < 2; c++) {
        const uint32_t st = slot + c * CHUNK_B;
        const int kc = 2 * stage + c;
        const size_t ao = ((size_t)mblk * KCA + kc) * 2048;
        const size_t bo = ((size_t)nblk * KCB + kc) * 2048;
        bulk4k(st,          Ah + ao, mbar);
        bulk4k(st + OFF_AL, Al + ao, mbar);
        bulk4k(st + OFF_BH, Bh + bo, mbar);
        bulk4k(st + OFF_BL, Bl + bo, mbar);
    }
}

// ---------------------------------------------------------------------------
// Fragment bundle (reused across sub-chunks)
// ---------------------------------------------------------------------------
struct Frags { uint32_t ah[4][4], al[4][4], bh[4][4], bl[4][4]; };

__device__ __forceinline__ void load_frags(Frags& f, uint32_t st,
        int wm, int wn, int arow, int achk, int brow, int bchk) {
#pragma unroll
    for (int i = 0; i < 4; i++) {
        const uint32_t o = swzb(wm + 16 * i + arow, achk);
        ldsm4(f.ah[i], st + o);
        ldsm4(f.al[i], st + OFF_AL + o);
    }
#pragma unroll
    for (int p = 0; p < 4; p++) {
        const uint32_t o = swzb(wn + 16 * p + brow, bchk);
        ldsm4(f.bh[p], st + OFF_BH + o);
        ldsm4(f.bl[p], st + OFF_BL + o);
    }
}

__device__ __forceinline__ void mma_frags(const Frags& f, float acc[4][8][4]) {
    // term 0: Ah*Bh
#pragma unroll
    for (int i = 0; i < 4; i++)
#pragma unroll
        for (int jj = 0; jj < 8; jj++) {
            const int p = jj >> 1, q = (jj & 1) * 2;
            mma_bf16(acc[i][jj], f.ah[i], f.bh[p][q], f.bh[p][q + 1]);
        }
    // term 1: Al*Bh
#pragma unroll
    for (int i = 0; i < 4; i++)
#pragma unroll
        for (int jj = 0; jj < 8; jj++) {
            const int p = jj >> 1, q = (jj & 1) * 2;
            mma_bf16(acc[i][jj], f.al[i], f.bh[p][q], f.bh[p][q + 1]);
        }
    // term 2: Ah*Bl
#pragma unroll
    for (int i = 0; i < 4; i++)
#pragma unroll
        for (int jj = 0; jj < 8; jj++) {
            const int p = jj >> 1, q = (jj & 1) * 2;
            mma_bf16(acc[i][jj], f.ah[i], f.bl[p][q], f.bl[p][q + 1]);
        }
}

// ---------------------------------------------------------------------------
// GEMM mainloop: C 128x128 block, 4 warps (2m x 2n, 64x64 warp tiles).
// NSTG=3 ring of grain-2 slots; stage t uses slot t%3, parity (t/3)&1.
// Round-11 ordering (measured best): wait -> ldsm(c0) -> MMA(c0) -> ldsm(c1)
// -> bar.sync -> tid0 refills stage t+3 into this slot -> MMA(c1).
// 96 KB smem + <=256 regs/thread => 2 CTAs/SM: the co-resident CTA's MMAs
// hide this CTA's wait/barrier bubbles.
// ---------------------------------------------------------------------------
__device__ void gemm_core(
    const bf16* __restrict__ Ahp, const bf16* __restrict__ Alp,
    const bf16* __restrict__ Bhp, const bf16* __restrict__ Blp,
    int mblk, int nblk, int KC, int KCA, int KCB, float acc[4][8][4])
{
    extern __shared__ char dsm[];
    __shared__ uint64_t mbars[NSTG];
    const uint32_t sb = (uint32_t)__cvta_generic_to_shared(dsm);
    const uint32_t mb0 = (uint32_t)__cvta_generic_to_shared(mbars);

    const int tid = threadIdx.x, lane = tid & 31, warp = tid >> 5;
    const int wm = (warp >> 1) * 64, wn = (warp & 1) * 64;

    const int arow = (lane & 7) + 8 * ((lane >> 3) & 1);
    const int achk = lane >> 4;
    const int brow = (lane & 7) + 8 * ((lane >> 4) & 1);
    const int bchk = (lane >> 3) & 1;

    const int KC2 = KC / 2;            // stages

    if (tid == 0) {
#pragma unroll
        for (int s = 0; s < NSTG; s++)
            asm volatile("mbarrier.init.shared.b64 [%0], %1;"
                         :: "r"(mb0 + 8 * s), "r"(1u) : "memory");
    }
    __syncthreads();

    if (tid == 0) {
#pragma unroll
        for (int i = 0; i < NSTG; i++)          // stages 0..2 (chunks 0..5)
            issue_slot(sb + i * SLOT_B, mb0 + 8 * i,
                       Ahp, Alp, Bhp, Blp, mblk, nblk, i, KCA, KCB);
    }

    Frags f;
    for (int t = 0; t < KC2; t++) {
        const int s = t % 3;
        const uint32_t par = (uint32_t)((t / 3) & 1);
        mbar_wait(mb0 + 8 * s, par);

        const uint32_t slot = sb + s * SLOT_B;

        // sub-chunk 0
        load_frags(f, slot, wm, wn, arow, achk, brow, bchk);
        mma_frags(f, acc);

        // sub-chunk 1 (all smem reads of this slot complete before barrier)
        load_frags(f, slot + CHUNK_B, wm, wn, arow, achk, brow, bchk);

        __syncthreads();

        const int j = t + NSTG;        // (j % 3) == s
        if (tid == 0 && j < KC2)
            issue_slot(slot, mb0 + 8 * s, Ahp, Alp, Bhp, Blp,
                       mblk, nblk, j, KCA, KCB);

        mma_frags(f, acc);
    }
}

// ---------------------------------------------------------------------------
// Conversion kernels (unchanged)
// ---------------------------------------------------------------------------
__global__ void convert_x_kernel(const float* __restrict__ x) {
    size_t i = ((size_t)blockIdx.x * 256 + threadIdx.x) * 4;
    const int m = (int)(i / D_), k = (int)(i % D_);
    float4 v = *(const float4*)(x + i);
    bf16 h0, l0, h1, l1, h2, l2, h3, l3;
    split1(v.x, h0, l0); split1(v.y, h1, l1);
    split1(v.z, h2, l2); split1(v.w, h3, l3);
    const size_t o = pk_off(m, k, D_ / 16);
    *(__nv_bfloat162*)(g_xh + o)     = __halves2bfloat162(h0, h1);
    *(__nv_bfloat162*)(g_xh + o + 2) = __halves2bfloat162(h2, h3);
    *(__nv_bfloat162*)(g_xl + o)     = __halves2bfloat162(l0, l1);
    *(__nv_bfloat162*)(g_xl + o + 2) = __halves2bfloat162(l2, l3);
}

__global__ void convert_Wt_kernel(const float* __restrict__ Wq,
                                  const float* __restrict__ Wk,
                                  const float* __restrict__ Wv) {
    const float* W = blockIdx.z == 0 ? Wq : blockIdx.z == 1 ? Wk : Wv;
    bf16* Oh = g_Wth[blockIdx.z];
    bf16* Ol = g_Wtl[blockIdx.z];
    __shared__ float t[32][33];
    const int k0 = blockIdx.y * 32, n0 = blockIdx.x * 32;
    const int tx = threadIdx.x, ty = threadIdx.y;
#pragma unroll
    for (int r = 0; r < 32; r += 8)
        t[ty + r][tx] = W[(size_t)(k0 + ty + r) * D_ + n0 + tx];
    __syncthreads();
#pragma unroll
    for (int r = 0; r < 32; r += 8) {
        float v = t[tx][ty + r];
        bf16 h, l; split1(v, h, l);
        const size_t o = pk_off(n0 + ty + r, k0 + tx, D_ / 16);
        Oh[o] = h; Ol[o] = l;
    }
}

__global__ void transpose_V_kernel() {
    __shared__ bf16 th[32][33], tl[32][33];
    const int b = blockIdx.z;
    const int t0 = blockIdx.x * 32, d0 = blockIdx.y * 32;
    const int tx = threadIdx.x, ty = threadIdx.y;
    const bf16* Vh = g_Vh + (size_t)b * S_ * D_;
    const bf16* Vl = g_Vl + (size_t)b * S_ * D_;
#pragma unroll
    for (int r = 0; r < 32; r += 8) {
        size_t o = (size_t)(t0 + ty + r) * D_ + d0 + tx;
        th[ty + r][tx] = Vh[o];
        tl[ty + r][tx] = Vl[o];
    }
    __syncthreads();
#pragma unroll
    for (int r = 0; r < 32; r += 8) {
        const size_t o = pk_off(b * D_ + d0 + ty + r, t0 + tx, S_ / 16);
        g_Vth[o] = th[tx][ty + r];
        g_Vtl[o] = tl[tx][ty + r];
    }
}

// ---------------------------------------------------------------------------
// GEMM 1: QKV projection. Q,K written packed; V written plain row-major.
// ---------------------------------------------------------------------------
__global__ __launch_bounds__(NTHREADS, 2) void gemm_proj_kernel(
    const float* __restrict__ bqp, const float* __restrict__ bkp,
    const float* __restrict__ bvp) {
    const int z = blockIdx.z;
    const float* bias = z == 0 ? bqp : z == 1 ? bkp : bvp;
    const int bm = blockIdx.y * 128, bn = blockIdx.x * 128;

    float acc[4][8][4] = {};
    gemm_core(g_xh, g_xl, g_Wth[z], g_Wtl[z],
              blockIdx.y, blockIdx.x, D_ / BK, D_ / 16, D_ / 16, acc);

    const int lane = threadIdx.x & 31, warp = threadIdx.x >> 5;
    const int wm = (warp >> 1) * 64, wn = (warp & 1) * 64;
    const int g = lane >> 2, t = lane & 3;
#pragma unroll
    for (int i = 0; i < 4; i++)
#pragma unroll
        for (int j = 0; j < 8; j++) {
            const int col = bn + wn + 8 * j + 2 * t;
            const float b0 = bias[col], b1 = bias[col + 1];
#pragma unroll
            for (int h2 = 0; h2 < 2; h2++) {
                const int r0 = bm + wm + 16 * i + g + 8 * h2;
                bf16 h0, l0, h1, l1;
                split1(acc[i][j][2 * h2 + 0] + b0, h0, l0);
                split1(acc[i][j][2 * h2 + 1] + b1, h1, l1);
                if (z < 2) {
                    bf16* Ch = z == 0 ? g_Qh : g_Kh;
                    bf16* Cl = z == 0 ? g_Ql : g_Kl;
                    const size_t o = pk_off(r0, col, D_ / 16);
                    *(__nv_bfloat162*)(Ch + o) = __halves2bfloat162(h0, h1);
                    *(__nv_bfloat162*)(Cl + o) = __halves2bfloat162(l0, l1);
                } else {
                    const size_t o = (size_t)r0 * D_ + col;
                    *(__nv_bfloat162*)(g_Vh + o) = __halves2bfloat162(h0, h1);
                    *(__nv_bfloat162*)(g_Vl + o) = __halves2bfloat162(l0, l1);
                }
            }
        }
}

// ---------------------------------------------------------------------------
// GEMM 2: scores = (Q @ K^T) * scale  (fp32 plain out)
// ---------------------------------------------------------------------------
__global__ __launch_bounds__(NTHREADS, 2) void gemm_scores_kernel() {
    const int b = blockIdx.z;
    const int bm = blockIdx.y * 128, bn = blockIdx.x * 128;

    float acc[4][8][4] = {};
    gemm_core(g_Qh, g_Ql, g_Kh, g_Kl,
              b * 16 + blockIdx.y, b * 16 + blockIdx.x,
              D_ / BK, D_ / 16, D_ / 16, acc);

    float* C = g_S + (size_t)b * S_ * S_;
    const int lane = threadIdx.x & 31, warp = threadIdx.x >> 5;
    const int wm = (warp >> 1) * 64, wn = (warp & 1) * 64;
    const int g = lane >> 2, t = lane & 3;
    const float sc = 0.03125f;
#pragma unroll
    for (int i = 0; i < 4; i++)
#pragma unroll
        for (int j = 0; j < 8; j++) {
            const int col = bn + wn + 8 * j + 2 * t;
            const int r0 = bm + wm + 16 * i + g;
            *(float2*)(C + (size_t)r0 * S_ + col) =
                make_float2(acc[i][j][0] * sc, acc[i][j][1] * sc);
            *(float2*)(C + (size_t)(r0 + 8) * S_ + col) =
                make_float2(acc[i][j][2] * sc, acc[i][j][3] * sc);
        }
}

// ---------------------------------------------------------------------------
// Softmax: fp32 scores -> packed attn bf16 hi/lo
// ---------------------------------------------------------------------------
__global__ __launch_bounds__(256) void softmax_kernel() {
    const int row = blockIdx.x;
    const float* p = g_S + (size_t)row * S_;
    const int tid = threadIdx.x;

    __shared__ float red[256];

    float v[8];
    float m = -INFINITY;
#pragma unroll
    for (int i = 0; i < 8; i++) {
        v[i] = p[tid + i * 256];
        m = fmaxf(m, v[i]);
    }
    red[tid] = m;
    __syncthreads();
    for (int s = 128; s > 0; s >>= 1) {
        if (tid < s) red[tid] = fmaxf(red[tid], red[tid + s]);
        __syncthreads();
    }
    m = red[0];
    __syncthreads();

    float sum = 0.f;
#pragma unroll
    for (int i = 0; i < 8; i++) {
        v[i] = __expf(v[i] - m);
        sum += v[i];
    }
    red[tid] = sum;
    __syncthreads();
    for (int s = 128; s > 0; s >>= 1) {
        if (tid < s) red[tid] += red[tid + s];
        __syncthreads();
    }
    const float inv = 1.0f / red[0];
#pragma unroll
    for (int i = 0; i < 8; i++) {
        bf16 h, l;
        split1(v[i] * inv, h, l);
        const size_t o = pk_off(row, tid + i * 256, S_ / 16);
        g_Ph[o] = h;
        g_Pl[o] = l;
    }
}

// ---------------------------------------------------------------------------
// GEMM 3: out = attn @ V  (fp32 plain out)
// ---------------------------------------------------------------------------
__global__ __launch_bounds__(NTHREADS, 2) void gemm_av_kernel(float* __restrict__ out) {
    const int b = blockIdx.z;
    const int bm = blockIdx.y * 128, bn = blockIdx.x * 128;

    float acc[4][8][4] = {};
    gemm_core(g_Ph, g_Pl, g_Vth, g_Vtl,
              b * 16 + blockIdx.y, b * 8 + blockIdx.x,
              S_ / BK, S_ / 16, S_ / 16, acc);

    float* C = out + (size_t)b * S_ * D_;
    const int lane = threadIdx.x & 31, warp = threadIdx.x >> 5;
    const int wm = (warp >> 1) * 64, wn = (warp & 1) * 64;
    const int g = lane >> 2, t = lane & 3;
#pragma unroll
    for (int i = 0; i < 4; i++)
#pragma unroll
        for (int j = 0; j < 8; j++) {
            const int col = bn + wn + 8 * j + 2 * t;
            const int r0 = bm + wm + 16 * i + g;
            *(float2*)(C + (size_t)r0 * D_ + col) =
                make_float2(acc[i][j][0], acc[i][j][1]);
            *(float2*)(C + (size_t)(r0 + 8) * D_ + col) =
                make_float2(acc[i][j][2], acc[i][j][3]);
        }
}

// ---------------------------------------------------------------------------
// Launch
// ---------------------------------------------------------------------------
extern "C" void kernel_launch(void* const* d_in, const int* in_sizes, int n_in,
                              void* d_out, int out_size) {
    const float* x  = (const float*)d_in[0];
    const float* Wq = (const float*)d_in[1];
    const float* bq = (const float*)d_in[2];
    const float* Wk = (const float*)d_in[3];
    const float* bk = (const float*)d_in[4];
    const float* Wv = (const float*)d_in[5];
    const float* bv = (const float*)d_in[6];
    float* out = (float*)d_out;

    cudaFuncSetAttribute(gemm_proj_kernel,
                         cudaFuncAttributeMaxDynamicSharedMemorySize, SMEM_DYN);
    cudaFuncSetAttribute(gemm_scores_kernel,
                         cudaFuncAttributeMaxDynamicSharedMemorySize, SMEM_DYN);
    cudaFuncSetAttribute(gemm_av_kernel,
                         cudaFuncAttributeMaxDynamicSharedMemorySize, SMEM_DYN);

    convert_x_kernel<<<(MS * D_) / 1024, 256>>>(x);
    convert_Wt_kernel<<<dim3(32, 32, 3), dim3(32, 8)>>>(Wq, Wk, Wv);

    gemm_proj_kernel<<<dim3(D_ / 128, MS / 128, 3), NTHREADS, SMEM_DYN>>>(bq, bk, bv);

    gemm_scores_kernel<<<dim3(S_ / 128, S_ / 128, B_), NTHREADS, SMEM_DYN>>>();

    transpose_V_kernel<<<dim3(S_ / 32, D_ / 32, B_), dim3(32, 8)>>>();

    softmax_kernel<<<B_ * S_, 256>>>();

    gemm_av_kernel<<<dim3(D_ / 128, S_ / 128, B_), NTHREADS, SMEM_DYN>>>(out);
}

// round 15
// speedup vs baseline: 1.1499x; 1.0120x over previous
#include <cuda_runtime.h>
#include <cuda_bf16.h>
#include <stdint.h>
#include <math.h>

#define B_  4
#define S_  2048
#define D_  1024
#define MS  (B_*S_)
#define BK  16
#define NSTG 3
#define OFF_AL 4096
#define OFF_BH 8192
#define OFF_BL 12288
#define CHUNK_B 16384                  // k16 chunk image: [Ah 4K][Al 4K][Bh 4K][Bl 4K]
#define SLOT_B (2*CHUNK_B)             // 32 KB: two consecutive k16 chunks
#define SMEM_DYN (NSTG*SLOT_B)         // 96 KB -> 2 CTAs/SM
#define NTHREADS 128                   // 4 warps, 2(m) x 2(n), warp tile 64x64

typedef __nv_bfloat16 bf16;

// ---------------------------------------------------------------------------
// Packed operand layout ("stage image"): [blk128][kchunk][swizzled 128x16]
// ---------------------------------------------------------------------------
__host__ __device__ __forceinline__ size_t pk_off(int r, int k, int KCtot) {
    const int u = (r & 127) * 2 + (((k >> 3) & 1) ^ ((r >> 2) & 1));
    return ((size_t)((r >> 7) * KCtot + (k >> 4)) * 2048) + (size_t)u * 8 + (k & 7);
}

__device__ __forceinline__ uint32_t swzb(int row, int chunk) {
    return (uint32_t)((row * 2 + (chunk ^ ((row >> 2) & 1))) * 16);
}

// ---------------------------------------------------------------------------
// Device-global scratch
// ---------------------------------------------------------------------------
__device__ bf16 g_xh[MS * D_], g_xl[MS * D_];                // packed, KCtot=64
__device__ bf16 g_Wth[3][D_ * D_], g_Wtl[3][D_ * D_];        // packed W^T, KCtot=64
__device__ bf16 g_Qh[MS * D_], g_Ql[MS * D_];                // packed, KCtot=64
__device__ bf16 g_Kh[MS * D_], g_Kl[MS * D_];                // packed, KCtot=64
__device__ bf16 g_Vh[MS * D_], g_Vl[MS * D_];                // PLAIN row-major [m][d]
__device__ bf16 g_Vth[MS * D_], g_Vtl[MS * D_];              // packed V^T, KCtot=128
__device__ float g_S[(size_t)B_ * S_ * S_];                  // plain fp32
__device__ bf16 g_Ph[(size_t)B_ * S_ * S_], g_Pl[(size_t)B_ * S_ * S_]; // packed, KCtot=128

// ---------------------------------------------------------------------------
// Helpers
// ---------------------------------------------------------------------------
__device__ __forceinline__ void split1(float v, bf16& h, bf16& l) {
    h = __float2bfloat16_rn(v);
    l = __float2bfloat16_rn(v - __bfloat162float(h));
}

__device__ __forceinline__ uint32_t pack2(bf16 a, bf16 b) {
    __nv_bfloat162 t = __halves2bfloat162(a, b);
    return *(uint32_t*)&t;
}

__device__ __forceinline__ void ldsm4(uint32_t r[4], uint32_t a) {
    asm volatile("ldmatrix.sync.aligned.m8n8.x4.shared.b16 {%0,%1,%2,%3}, [%4];"
                 : "=r"(r[0]), "=r"(r[1]), "=r"(r[2]), "=r"(r[3]) : "r"(a));
}

__device__ __forceinline__ void mma_bf16(float c[4], const uint32_t a[4],
                                         const uint32_t b0, const uint32_t b1) {
    asm volatile(
        "mma.sync.aligned.m16n8k16.row.col.f32.bf16.bf16.f32 "
        "{%0,%1,%2,%3},{%4,%5,%6,%7},{%8,%9},{%0,%1,%2,%3};"
        : "+f"(c[0]), "+f"(c[1]), "+f"(c[2]), "+f"(c[3])
        : "r"(a[0]), "r"(a[1]), "r"(a[2]), "r"(a[3]), "r"(b0), "r"(b1));
}

__device__ __forceinline__ void bulk4k(uint32_t dst, const void* src, uint32_t mbar) {
    asm volatile(
        "cp.async.bulk.shared::cluster.global.mbarrier::complete_tx::bytes "
        "[%0], [%1], 4096, [%2];"
        :: "r"(dst), "l"(src), "r"(mbar) : "memory");
}

__device__ __forceinline__ void mbar_wait(uint32_t mbar, uint32_t parity) {
    uint32_t done;
    asm volatile(
        "{\n\t.reg .pred p;\n\t"
        "mbarrier.try_wait.parity.acquire.cta.shared::cta.b64 p, [%1], %2;\n\t"
        "selp.b32 %0, 1, 0, p;\n\t}"
        : "=r"(done) : "r"(mbar), "r"(parity) : "memory");
    if (!done) {
        asm volatile(
            "{\n\t.reg .pred P1;\n\t"
            "WAIT_LOOP_%=:\n\t"
            "mbarrier.try_wait.parity.acquire.cta.shared::cta.b64 P1, [%0], %1, 0x989680;\n\t"
            "@P1 bra.uni WAIT_DONE_%=;\n\t"
            "bra.uni WAIT_LOOP_%=;\n\t"
            "WAIT_DONE_%=:\n\t}"
            :: "r"(mbar), "r"(parity) : "memory");
    }
}

// ---------------------------------------------------------------------------
// Slot issue: one thread, 8 x 4KB bulk copies (two k16 chunks) per slot
// ---------------------------------------------------------------------------
__device__ __forceinline__ void issue_slot(uint32_t slot, uint32_t mbar,
        const bf16* __restrict__ Ah, const bf16* __restrict__ Al,
        const bf16* __restrict__ Bh, const bf16* __restrict__ Bl,
        int mblk, int nblk, int stage, int KCA, int KCB) {
    asm volatile("mbarrier.arrive.expect_tx.shared.b64 _, [%0], %1;"
                 :: "r"(mbar), "r"(32768u) : "memory");
#pragma unroll
    for (int c = 0; c < 2; c++) {
        const uint32_t st = slot + c * CHUNK_B;
        const int kc = 2 * stage + c;
        const size_t ao = ((size_t)mblk * KCA + kc) * 2048;
        const size_t bo = ((size_t)nblk * KCB + kc) * 2048;
        bulk4k(st,          Ah + ao, mbar);
        bulk4k(st + OFF_AL, Al + ao, mbar);
        bulk4k(st + OFF_BH, Bh + bo, mbar);
        bulk4k(st + OFF_BL, Bl + bo, mbar);
    }
}

// ---------------------------------------------------------------------------
// Fragment bundle (reused across sub-chunks)
// ---------------------------------------------------------------------------
struct Frags { uint32_t ah[4][4], al[4][4], bh[4][4], bl[4][4]; };

__device__ __forceinline__ void load_frags(Frags& f, uint32_t st,
        int wm, int wn, int arow, int achk, int brow, int bchk) {
#pragma unroll
    for (int i = 0; i < 4; i++) {
        const uint32_t o = swzb(wm + 16 * i + arow, achk);
        ldsm4(f.ah[i], st + o);
        ldsm4(f.al[i], st + OFF_AL + o);
    }
#pragma unroll
    for (int p = 0; p < 4; p++) {
        const uint32_t o = swzb(wn + 16 * p + brow, bchk);
        ldsm4(f.bh[p], st + OFF_BH + o);
        ldsm4(f.bl[p], st + OFF_BL + o);
    }
}

__device__ __forceinline__ void mma_frags(const Frags& f, float acc[4][8][4]) {
    // term 0: Ah*Bh
#pragma unroll
    for (int i = 0; i < 4; i++)
#pragma unroll
        for (int jj = 0; jj < 8; jj++) {
            const int p = jj >> 1, q = (jj & 1) * 2;
            mma_bf16(acc[i][jj], f.ah[i], f.bh[p][q], f.bh[p][q + 1]);
        }
    // term 1: Al*Bh
#pragma unroll
    for (int i = 0; i < 4; i++)
#pragma unroll
        for (int jj = 0; jj < 8; jj++) {
            const int p = jj >> 1, q = (jj & 1) * 2;
            mma_bf16(acc[i][jj], f.al[i], f.bh[p][q], f.bh[p][q + 1]);
        }
    // term 2: Ah*Bl
#pragma unroll
    for (int i = 0; i < 4; i++)
#pragma unroll
        for (int jj = 0; jj < 8; jj++) {
            const int p = jj >> 1, q = (jj & 1) * 2;
            mma_bf16(acc[i][jj], f.ah[i], f.bl[p][q], f.bl[p][q + 1]);
        }
}

// ---------------------------------------------------------------------------
// GEMM mainloop: C 128x128 block, 4 warps (2m x 2n, 64x64 warp tiles).
// NSTG=3 ring of grain-2 slots; stage t uses slot t%3, parity (t/3)&1.
// Measured-best ordering: wait -> ldsm(c0) -> MMA(c0) -> ldsm(c1) -> bar ->
// tid0 refills stage t+3 into this slot -> MMA(c1).
// 96 KB smem + ~225 regs => 2 CTAs/SM hides wait/barrier bubbles.
// ---------------------------------------------------------------------------
__device__ void gemm_core(
    const bf16* __restrict__ Ahp, const bf16* __restrict__ Alp,
    const bf16* __restrict__ Bhp, const bf16* __restrict__ Blp,
    int mblk, int nblk, int KC, int KCA, int KCB, float acc[4][8][4])
{
    extern __shared__ char dsm[];
    __shared__ uint64_t mbars[NSTG];
    const uint32_t sb = (uint32_t)__cvta_generic_to_shared(dsm);
    const uint32_t mb0 = (uint32_t)__cvta_generic_to_shared(mbars);

    const int tid = threadIdx.x, lane = tid & 31, warp = tid >> 5;
    const int wm = (warp >> 1) * 64, wn = (warp & 1) * 64;

    const int arow = (lane & 7) + 8 * ((lane >> 3) & 1);
    const int achk = lane >> 4;
    const int brow = (lane & 7) + 8 * ((lane >> 4) & 1);
    const int bchk = (lane >> 3) & 1;

    const int KC2 = KC / 2;            // stages

    if (tid == 0) {
#pragma unroll
        for (int s = 0; s < NSTG; s++)
            asm volatile("mbarrier.init.shared.b64 [%0], %1;"
                         :: "r"(mb0 + 8 * s), "r"(1u) : "memory");
    }
    __syncthreads();

    if (tid == 0) {
#pragma unroll
        for (int i = 0; i < NSTG; i++)          // stages 0..2 (chunks 0..5)
            issue_slot(sb + i * SLOT_B, mb0 + 8 * i,
                       Ahp, Alp, Bhp, Blp, mblk, nblk, i, KCA, KCB);
    }

    Frags f;
    for (int t = 0; t < KC2; t++) {
        const int s = t % 3;
        const uint32_t par = (uint32_t)((t / 3) & 1);
        mbar_wait(mb0 + 8 * s, par);

        const uint32_t slot = sb + s * SLOT_B;

        // sub-chunk 0
        load_frags(f, slot, wm, wn, arow, achk, brow, bchk);
        mma_frags(f, acc);

        // sub-chunk 1 (all smem reads of this slot complete before barrier)
        load_frags(f, slot + CHUNK_B, wm, wn, arow, achk, brow, bchk);

        __syncthreads();

        const int j = t + NSTG;        // (j % 3) == s
        if (tid == 0 && j < KC2)
            issue_slot(slot, mb0 + 8 * s, Ahp, Alp, Bhp, Blp,
                       mblk, nblk, j, KCA, KCB);

        mma_frags(f, acc);
    }
}

// ---------------------------------------------------------------------------
// convert_x: thread owns 8 consecutive elements -> uint4 packed stores
// ---------------------------------------------------------------------------
__global__ __launch_bounds__(256) void convert_x_kernel(const float* __restrict__ x) {
    const size_t i = ((size_t)blockIdx.x * 256 + threadIdx.x) * 8;
    const int m = (int)(i / D_), k = (int)(i % D_);
    float4 a = *(const float4*)(x + i);
    float4 b = *(const float4*)(x + i + 4);
    float v[8] = {a.x, a.y, a.z, a.w, b.x, b.y, b.z, b.w};
    uint32_t hw[4], lw[4];
#pragma unroll
    for (int q = 0; q < 4; q++) {
        bf16 h0, l0, h1, l1;
        split1(v[2 * q], h0, l0);
        split1(v[2 * q + 1], h1, l1);
        hw[q] = pack2(h0, h1);
        lw[q] = pack2(l0, l1);
    }
    const size_t o = pk_off(m, k, D_ / 16);    // k % 8 == 0 -> 16B-aligned group
    *(uint4*)(g_xh + o) = make_uint4(hw[0], hw[1], hw[2], hw[3]);
    *(uint4*)(g_xl + o) = make_uint4(lw[0], lw[1], lw[2], lw[3]);
}

__global__ void convert_Wt_kernel(const float* __restrict__ Wq,
                                  const float* __restrict__ Wk,
                                  const float* __restrict__ Wv) {
    const float* W = blockIdx.z == 0 ? Wq : blockIdx.z == 1 ? Wk : Wv;
    bf16* Oh = g_Wth[blockIdx.z];
    bf16* Ol = g_Wtl[blockIdx.z];
    __shared__ float t[32][33];
    const int k0 = blockIdx.y * 32, n0 = blockIdx.x * 32;
    const int tx = threadIdx.x, ty = threadIdx.y;
#pragma unroll
    for (int r = 0; r < 32; r += 8)
        t[ty + r][tx] = W[(size_t)(k0 + ty + r) * D_ + n0 + tx];
    __syncthreads();
#pragma unroll
    for (int r = 0; r < 32; r += 8) {
        float v = t[tx][ty + r];
        bf16 h, l; split1(v, h, l);
        const size_t o = pk_off(n0 + ty + r, k0 + tx, D_ / 16);
        Oh[o] = h; Ol[o] = l;
    }
}

__global__ void transpose_V_kernel() {
    __shared__ bf16 th[32][33], tl[32][33];
    const int b = blockIdx.z;
    const int t0 = blockIdx.x * 32, d0 = blockIdx.y * 32;
    const int tx = threadIdx.x, ty = threadIdx.y;
    const bf16* Vh = g_Vh + (size_t)b * S_ * D_;
    const bf16* Vl = g_Vl + (size_t)b * S_ * D_;
#pragma unroll
    for (int r = 0; r < 32; r += 8) {
        size_t o = (size_t)(t0 + ty + r) * D_ + d0 + tx;
        th[ty + r][tx] = Vh[o];
        tl[ty + r][tx] = Vl[o];
    }
    __syncthreads();
#pragma unroll
    for (int r = 0; r < 32; r += 8) {
        const size_t o = pk_off(b * D_ + d0 + ty + r, t0 + tx, S_ / 16);
        g_Vth[o] = th[tx][ty + r];
        g_Vtl[o] = tl[tx][ty + r];
    }
}

// ---------------------------------------------------------------------------
// GEMM 1: QKV projection. Q,K written packed; V written plain row-major.
// ---------------------------------------------------------------------------
__global__ __launch_bounds__(NTHREADS, 2) void gemm_proj_kernel(
    const float* __restrict__ bqp, const float* __restrict__ bkp,
    const float* __restrict__ bvp) {
    const int z = blockIdx.z;
    const float* bias = z == 0 ? bqp : z == 1 ? bkp : bvp;
    const int bm = blockIdx.y * 128, bn = blockIdx.x * 128;

    float acc[4][8][4] = {};
    gemm_core(g_xh, g_xl, g_Wth[z], g_Wtl[z],
              blockIdx.y, blockIdx.x, D_ / BK, D_ / 16, D_ / 16, acc);

    const int lane = threadIdx.x & 31, warp = threadIdx.x >> 5;
    const int wm = (warp >> 1) * 64, wn = (warp & 1) * 64;
    const int g = lane >> 2, t = lane & 3;
#pragma unroll
    for (int i = 0; i < 4; i++)
#pragma unroll
        for (int j = 0; j < 8; j++) {
            const int col = bn + wn + 8 * j + 2 * t;
            const float b0 = bias[col], b1 = bias[col + 1];
#pragma unroll
            for (int h2 = 0; h2 < 2; h2++) {
                const int r0 = bm + wm + 16 * i + g + 8 * h2;
                bf16 h0, l0, h1, l1;
                split1(acc[i][j][2 * h2 + 0] + b0, h0, l0);
                split1(acc[i][j][2 * h2 + 1] + b1, h1, l1);
                if (z < 2) {
                    bf16* Ch = z == 0 ? g_Qh : g_Kh;
                    bf16* Cl = z == 0 ? g_Ql : g_Kl;
                    const size_t o = pk_off(r0, col, D_ / 16);
                    *(__nv_bfloat162*)(Ch + o) = __halves2bfloat162(h0, h1);
                    *(__nv_bfloat162*)(Cl + o) = __halves2bfloat162(l0, l1);
                } else {
                    const size_t o = (size_t)r0 * D_ + col;
                    *(__nv_bfloat162*)(g_Vh + o) = __halves2bfloat162(h0, h1);
                    *(__nv_bfloat162*)(g_Vl + o) = __halves2bfloat162(l0, l1);
                }
            }
        }
}

// ---------------------------------------------------------------------------
// GEMM 2: scores = (Q @ K^T) * scale  (fp32 plain out)
// ---------------------------------------------------------------------------
__global__ __launch_bounds__(NTHREADS, 2) void gemm_scores_kernel() {
    const int b = blockIdx.z;
    const int bm = blockIdx.y * 128, bn = blockIdx.x * 128;

    float acc[4][8][4] = {};
    gemm_core(g_Qh, g_Ql, g_Kh, g_Kl,
              b * 16 + blockIdx.y, b * 16 + blockIdx.x,
              D_ / BK, D_ / 16, D_ / 16, acc);

    float* C = g_S + (size_t)b * S_ * S_;
    const int lane = threadIdx.x & 31, warp = threadIdx.x >> 5;
    const int wm = (warp >> 1) * 64, wn = (warp & 1) * 64;
    const int g = lane >> 2, t = lane & 3;
    const float sc = 0.03125f;
#pragma unroll
    for (int i = 0; i < 4; i++)
#pragma unroll
        for (int j = 0; j < 8; j++) {
            const int col = bn + wn + 8 * j + 2 * t;
            const int r0 = bm + wm + 16 * i + g;
            *(float2*)(C + (size_t)r0 * S_ + col) =
                make_float2(acc[i][j][0] * sc, acc[i][j][1] * sc);
            *(float2*)(C + (size_t)(r0 + 8) * S_ + col) =
                make_float2(acc[i][j][2] * sc, acc[i][j][3] * sc);
        }
}

// ---------------------------------------------------------------------------
// Softmax: fp32 scores -> packed attn bf16 hi/lo.
// Thread owns 8 CONSECUTIVE k: float4 loads, warp-shuffle reductions
// (2 barriers total), and one 16B uint4 store per output array
// (pk_off(row, k0) with k0 % 8 == 0 is a contiguous aligned 8-bf16 group).
// ---------------------------------------------------------------------------
__global__ __launch_bounds__(256) void softmax_kernel() {
    const int row = blockIdx.x;
    const float* p = g_S + (size_t)row * S_;
    const int tid = threadIdx.x;
    const int lane = tid & 31, warp = tid >> 5;
    const int k0 = tid * 8;

    __shared__ float red[16];

    float4 a = *(const float4*)(p + k0);
    float4 b = *(const float4*)(p + k0 + 4);
    float v[8] = {a.x, a.y, a.z, a.w, b.x, b.y, b.z, b.w};

    float m = v[0];
#pragma unroll
    for (int i = 1; i < 8; i++) m = fmaxf(m, v[i]);
#pragma unroll
    for (int off = 16; off > 0; off >>= 1)
        m = fmaxf(m, __shfl_xor_sync(0xFFFFFFFFu, m, off));
    if (lane == 0) red[warp] = m;
    __syncthreads();
    m = red[0];
#pragma unroll
    for (int w = 1; w < 8; w++) m = fmaxf(m, red[w]);

    float sum = 0.f;
#pragma unroll
    for (int i = 0; i < 8; i++) {
        v[i] = __expf(v[i] - m);
        sum += v[i];
    }
#pragma unroll
    for (int off = 16; off > 0; off >>= 1)
        sum += __shfl_xor_sync(0xFFFFFFFFu, sum, off);
    if (lane == 0) red[8 + warp] = sum;
    __syncthreads();
    float tot = red[8];
#pragma unroll
    for (int w = 1; w < 8; w++) tot += red[8 + w];
    const float inv = 1.0f / tot;

    uint32_t hw[4], lw[4];
#pragma unroll
    for (int q = 0; q < 4; q++) {
        bf16 h0, l0, h1, l1;
        split1(v[2 * q] * inv, h0, l0);
        split1(v[2 * q + 1] * inv, h1, l1);
        hw[q] = pack2(h0, h1);
        lw[q] = pack2(l0, l1);
    }
    const size_t o = pk_off(row, k0, S_ / 16);
    *(uint4*)(g_Ph + o) = make_uint4(hw[0], hw[1], hw[2], hw[3]);
    *(uint4*)(g_Pl + o) = make_uint4(lw[0], lw[1], lw[2], lw[3]);
}

// ---------------------------------------------------------------------------
// GEMM 3: out = attn @ V  (fp32 plain out)
// ---------------------------------------------------------------------------
__global__ __launch_bounds__(NTHREADS, 2) void gemm_av_kernel(float* __restrict__ out) {
    const int b = blockIdx.z;
    const int bm = blockIdx.y * 128, bn = blockIdx.x * 128;

    float acc[4][8][4] = {};
    gemm_core(g_Ph, g_Pl, g_Vth, g_Vtl,
              b * 16 + blockIdx.y, b * 8 + blockIdx.x,
              S_ / BK, S_ / 16, S_ / 16, acc);

    float* C = out + (size_t)b * S_ * D_;
    const int lane = threadIdx.x & 31, warp = threadIdx.x >> 5;
    const int wm = (warp >> 1) * 64, wn = (warp & 1) * 64;
    const int g = lane >> 2, t = lane & 3;
#pragma unroll
    for (int i = 0; i < 4; i++)
#pragma unroll
        for (int j = 0; j < 8; j++) {
            const int col = bn + wn + 8 * j + 2 * t;
            const int r0 = bm + wm + 16 * i + g;
            *(float2*)(C + (size_t)r0 * D_ + col) =
                make_float2(acc[i][j][0], acc[i][j][1]);
            *(float2*)(C + (size_t)(r0 + 8) * D_ + col) =
                make_float2(acc[i][j][2], acc[i][j][3]);
        }
}

// ---------------------------------------------------------------------------
// Launch
// ---------------------------------------------------------------------------
extern "C" void kernel_launch(void* const* d_in, const int* in_sizes, int n_in,
                              void* d_out, int out_size) {
    const float* x  = (const float*)d_in[0];
    const float* Wq = (const float*)d_in[1];
    const float* bq = (const float*)d_in[2];
    const float* Wk = (const float*)d_in[3];
    const float* bk = (const float*)d_in[4];
    const float* Wv = (const float*)d_in[5];
    const float* bv = (const float*)d_in[6];
    float* out = (float*)d_out;

    cudaFuncSetAttribute(gemm_proj_kernel,
                         cudaFuncAttributeMaxDynamicSharedMemorySize, SMEM_DYN);
    cudaFuncSetAttribute(gemm_scores_kernel,
                         cudaFuncAttributeMaxDynamicSharedMemorySize, SMEM_DYN);
    cudaFuncSetAttribute(gemm_av_kernel,
                         cudaFuncAttributeMaxDynamicSharedMemorySize, SMEM_DYN);

    convert_x_kernel<<<(MS * D_) / 2048, 256>>>(x);
    convert_Wt_kernel<<<dim3(32, 32, 3), dim3(32, 8)>>>(Wq, Wk, Wv);

    gemm_proj_kernel<<<dim3(D_ / 128, MS / 128, 3), NTHREADS, SMEM_DYN>>>(bq, bk, bv);

    gemm_scores_kernel<<<dim3(S_ / 128, S_ / 128, B_), NTHREADS, SMEM_DYN>>>();

    transpose_V_kernel<<<dim3(S_ / 32, D_ / 32, B_), dim3(32, 8)>>>();

    softmax_kernel<<<B_ * S_, 256>>>();

    gemm_av_kernel<<<dim3(D_ / 128, S_ / 128, B_), NTHREADS, SMEM_DYN>>>(out);
}

// round 17
// speedup vs baseline: 1.2138x; 1.0556x over previous
#include <cuda_runtime.h>
#include <cuda_bf16.h>
#include <stdint.h>
#include <math.h>

#define B_  4
#define S_  2048
#define D_  1024
#define MS  (B_*S_)
#define BK  16
#define NSTG 3
#define OFF_AL 4096
#define OFF_BH 8192
#define OFF_BL 12288
#define CHUNK_B 16384                  // k16 chunk image: [Ah 4K][Al 4K][Bh 4K][Bl 4K]
#define SLOT_B (2*CHUNK_B)             // 32 KB: two consecutive k16 chunks
#define SMEM_DYN (NSTG*SLOT_B)         // 96 KB -> 2 CTAs/SM
#define NTHREADS 128                   // 4 warps, 2(m) x 2(n), warp tile 64x64
#define TSTRIDE 136                    // padded V^T staging row stride (elems)

typedef __nv_bfloat16 bf16;

// ---------------------------------------------------------------------------
// Packed operand layout ("stage image"): [blk128][kchunk][swizzled 128x16]
// ---------------------------------------------------------------------------
__host__ __device__ __forceinline__ size_t pk_off(int r, int k, int KCtot) {
    const int u = (r & 127) * 2 + (((k >> 3) & 1) ^ ((r >> 2) & 1));
    return ((size_t)((r >> 7) * KCtot + (k >> 4)) * 2048) + (size_t)u * 8 + (k & 7);
}

__device__ __forceinline__ uint32_t swzb(int row, int chunk) {
    return (uint32_t)((row * 2 + (chunk ^ ((row >> 2) & 1))) * 16);
}

// ---------------------------------------------------------------------------
// Device-global scratch
// ---------------------------------------------------------------------------
__device__ bf16 g_xh[MS * D_], g_xl[MS * D_];                // packed, KCtot=64
__device__ bf16 g_Wth[3][D_ * D_], g_Wtl[3][D_ * D_];        // packed W^T, KCtot=64
__device__ bf16 g_Qh[MS * D_], g_Ql[MS * D_];                // packed, KCtot=64
__device__ bf16 g_Kh[MS * D_], g_Kl[MS * D_];                // packed, KCtot=64
__device__ bf16 g_Vth[MS * D_], g_Vtl[MS * D_];              // packed V^T, KCtot=128
__device__ float g_S[(size_t)B_ * S_ * S_];                  // plain fp32
__device__ bf16 g_Ph[(size_t)B_ * S_ * S_], g_Pl[(size_t)B_ * S_ * S_]; // packed, KCtot=128

// ---------------------------------------------------------------------------
// Helpers
// ---------------------------------------------------------------------------
__device__ __forceinline__ void split1(float v, bf16& h, bf16& l) {
    h = __float2bfloat16_rn(v);
    l = __float2bfloat16_rn(v - __bfloat162float(h));
}

__device__ __forceinline__ uint32_t pack2(bf16 a, bf16 b) {
    __nv_bfloat162 t = __halves2bfloat162(a, b);
    return *(uint32_t*)&t;
}

__device__ __forceinline__ void ldsm4(uint32_t r[4], uint32_t a) {
    asm volatile("ldmatrix.sync.aligned.m8n8.x4.shared.b16 {%0,%1,%2,%3}, [%4];"
                 : "=r"(r[0]), "=r"(r[1]), "=r"(r[2]), "=r"(r[3]) : "r"(a));
}

__device__ __forceinline__ void mma_bf16(float c[4], const uint32_t a[4],
                                         const uint32_t b0, const uint32_t b1) {
    asm volatile(
        "mma.sync.aligned.m16n8k16.row.col.f32.bf16.bf16.f32 "
        "{%0,%1,%2,%3},{%4,%5,%6,%7},{%8,%9},{%0,%1,%2,%3};"
        : "+f"(c[0]), "+f"(c[1]), "+f"(c[2]), "+f"(c[3])
        : "r"(a[0]), "r"(a[1]), "r"(a[2]), "r"(a[3]), "r"(b0), "r"(b1));
}

__device__ __forceinline__ void bulk4k(uint32_t dst, const void* src, uint32_t mbar) {
    asm volatile(
        "cp.async.bulk.shared::cluster.global.mbarrier::complete_tx::bytes "
        "[%0], [%1], 4096, [%2];"
        :: "r"(dst), "l"(src), "r"(mbar) : "memory");
}

__device__ __forceinline__ void mbar_wait(uint32_t mbar, uint32_t parity) {
    uint32_t done;
    asm volatile(
        "{\n\t.reg .pred p;\n\t"
        "mbarrier.try_wait.parity.acquire.cta.shared::cta.b64 p, [%1], %2;\n\t"
        "selp.b32 %0, 1, 0, p;\n\t}"
        : "=r"(done) : "r"(mbar), "r"(parity) : "memory");
    if (!done) {
        asm volatile(
            "{\n\t.reg .pred P1;\n\t"
            "WAIT_LOOP_%=:\n\t"
            "mbarrier.try_wait.parity.acquire.cta.shared::cta.b64 P1, [%0], %1, 0x989680;\n\t"
            "@P1 bra.uni WAIT_DONE_%=;\n\t"
            "bra.uni WAIT_LOOP_%=;\n\t"
            "WAIT_DONE_%=:\n\t}"
            :: "r"(mbar), "r"(parity) : "memory");
    }
}

// ---------------------------------------------------------------------------
// Slot issue: one thread, 8 x 4KB bulk copies (two k16 chunks) per slot
// ---------------------------------------------------------------------------
__device__ __forceinline__ void issue_slot(uint32_t slot, uint32_t mbar,
        const bf16* __restrict__ Ah, const bf16* __restrict__ Al,
        const bf16* __restrict__ Bh, const bf16* __restrict__ Bl,
        int mblk, int nblk, int stage, int KCA, int KCB) {
    asm volatile("mbarrier.arrive.expect_tx.shared.b64 _, [%0], %1;"
                 :: "r"(mbar), "r"(32768u) : "memory");
#pragma unroll
    for (int c = 0; c < 2; c++) {
        const uint32_t st = slot + c * CHUNK_B;
        const int kc = 2 * stage + c;
        const size_t ao = ((size_t)mblk * KCA + kc) * 2048;
        const size_t bo = ((size_t)nblk * KCB + kc) * 2048;
        bulk4k(st,          Ah + ao, mbar);
        bulk4k(st + OFF_AL, Al + ao, mbar);
        bulk4k(st + OFF_BH, Bh + bo, mbar);
        bulk4k(st + OFF_BL, Bl + bo, mbar);
    }
}

// ---------------------------------------------------------------------------
// Fragment bundle (reused across sub-chunks)
// ---------------------------------------------------------------------------
struct Frags { uint32_t ah[4][4], al[4][4], bh[4][4], bl[4][4]; };

__device__ __forceinline__ void load_frags(Frags& f, uint32_t st,
        int wm, int wn, int arow, int achk, int brow, int bchk) {
#pragma unroll
    for (int i = 0; i < 4; i++) {
        const uint32_t o = swzb(wm + 16 * i + arow, achk);
        ldsm4(f.ah[i], st + o);
        ldsm4(f.al[i], st + OFF_AL + o);
    }
#pragma unroll
    for (int p = 0; p < 4; p++) {
        const uint32_t o = swzb(wn + 16 * p + brow, bchk);
        ldsm4(f.bh[p], st + OFF_BH + o);
        ldsm4(f.bl[p], st + OFF_BL + o);
    }
}

__device__ __forceinline__ void mma_frags(const Frags& f, float acc[4][8][4]) {
    // term 0: Ah*Bh
#pragma unroll
    for (int i = 0; i < 4; i++)
#pragma unroll
        for (int jj = 0; jj < 8; jj++) {
            const int p = jj >> 1, q = (jj & 1) * 2;
            mma_bf16(acc[i][jj], f.ah[i], f.bh[p][q], f.bh[p][q + 1]);
        }
    // term 1: Al*Bh
#pragma unroll
    for (int i = 0; i < 4; i++)
#pragma unroll
        for (int jj = 0; jj < 8; jj++) {
            const int p = jj >> 1, q = (jj & 1) * 2;
            mma_bf16(acc[i][jj], f.al[i], f.bh[p][q], f.bh[p][q + 1]);
        }
    // term 2: Ah*Bl
#pragma unroll
    for (int i = 0; i < 4; i++)
#pragma unroll
        for (int jj = 0; jj < 8; jj++) {
            const int p = jj >> 1, q = (jj & 1) * 2;
            mma_bf16(acc[i][jj], f.ah[i], f.bl[p][q], f.bl[p][q + 1]);
        }
}

// ---------------------------------------------------------------------------
// GEMM mainloop: C 128x128 block, 4 warps (2m x 2n, 64x64 warp tiles).
// NSTG=3 ring of grain-2 slots; stage t uses slot t%3, parity (t/3)&1.
// Measured-best ordering: wait -> ldsm(c0) -> MMA(c0) -> ldsm(c1) -> bar ->
// tid0 refills stage t+3 into this slot -> MMA(c1). 2 CTAs/SM.
// ---------------------------------------------------------------------------
__device__ void gemm_core(
    const bf16* __restrict__ Ahp, const bf16* __restrict__ Alp,
    const bf16* __restrict__ Bhp, const bf16* __restrict__ Blp,
    int mblk, int nblk, int KC, int KCA, int KCB, float acc[4][8][4])
{
    extern __shared__ char dsm[];
    __shared__ uint64_t mbars[NSTG];
    const uint32_t sb = (uint32_t)__cvta_generic_to_shared(dsm);
    const uint32_t mb0 = (uint32_t)__cvta_generic_to_shared(mbars);

    const int tid = threadIdx.x, lane = tid & 31, warp = tid >> 5;
    const int wm = (warp >> 1) * 64, wn = (warp & 1) * 64;

    const int arow = (lane & 7) + 8 * ((lane >> 3) & 1);
    const int achk = lane >> 4;
    const int brow = (lane & 7) + 8 * ((lane >> 4) & 1);
    const int bchk = (lane >> 3) & 1;

    const int KC2 = KC / 2;            // stages

    if (tid == 0) {
#pragma unroll
        for (int s = 0; s < NSTG; s++)
            asm volatile("mbarrier.init.shared.b64 [%0], %1;"
                         :: "r"(mb0 + 8 * s), "r"(1u) : "memory");
    }
    __syncthreads();

    if (tid == 0) {
#pragma unroll
        for (int i = 0; i < NSTG; i++)          // stages 0..2 (chunks 0..5)
            issue_slot(sb + i * SLOT_B, mb0 + 8 * i,
                       Ahp, Alp, Bhp, Blp, mblk, nblk, i, KCA, KCB);
    }

    Frags f;
    for (int t = 0; t < KC2; t++) {
        const int s = t % 3;
        const uint32_t par = (uint32_t)((t / 3) & 1);
        mbar_wait(mb0 + 8 * s, par);

        const uint32_t slot = sb + s * SLOT_B;

        // sub-chunk 0
        load_frags(f, slot, wm, wn, arow, achk, brow, bchk);
        mma_frags(f, acc);

        // sub-chunk 1 (all smem reads of this slot complete before barrier)
        load_frags(f, slot + CHUNK_B, wm, wn, arow, achk, brow, bchk);

        __syncthreads();

        const int j = t + NSTG;        // (j % 3) == s
        if (tid == 0 && j < KC2)
            issue_slot(slot, mb0 + 8 * s, Ahp, Alp, Bhp, Blp,
                       mblk, nblk, j, KCA, KCB);

        mma_frags(f, acc);
    }
}

// ---------------------------------------------------------------------------
// convert_x: thread owns 8 consecutive elements -> uint4 packed stores
// ---------------------------------------------------------------------------
__global__ __launch_bounds__(256) void convert_x_kernel(const float* __restrict__ x) {
    const size_t i = ((size_t)blockIdx.x * 256 + threadIdx.x) * 8;
    const int m = (int)(i / D_), k = (int)(i % D_);
    float4 a = *(const float4*)(x + i);
    float4 b = *(const float4*)(x + i + 4);
    float v[8] = {a.x, a.y, a.z, a.w, b.x, b.y, b.z, b.w};
    uint32_t hw[4], lw[4];
#pragma unroll
    for (int q = 0; q < 4; q++) {
        bf16 h0, l0, h1, l1;
        split1(v[2 * q], h0, l0);
        split1(v[2 * q + 1], h1, l1);
        hw[q] = pack2(h0, h1);
        lw[q] = pack2(l0, l1);
    }
    const size_t o = pk_off(m, k, D_ / 16);
    *(uint4*)(g_xh + o) = make_uint4(hw[0], hw[1], hw[2], hw[3]);
    *(uint4*)(g_xl + o) = make_uint4(lw[0], lw[1], lw[2], lw[3]);
}

__global__ void convert_Wt_kernel(const float* __restrict__ Wq,
                                  const float* __restrict__ Wk,
                                  const float* __restrict__ Wv) {
    const float* W = blockIdx.z == 0 ? Wq : blockIdx.z == 1 ? Wk : Wv;
    bf16* Oh = g_Wth[blockIdx.z];
    bf16* Ol = g_Wtl[blockIdx.z];
    __shared__ float t[32][33];
    const int k0 = blockIdx.y * 32, n0 = blockIdx.x * 32;
    const int tx = threadIdx.x, ty = threadIdx.y;
#pragma unroll
    for (int r = 0; r < 32; r += 8)
        t[ty + r][tx] = W[(size_t)(k0 + ty + r) * D_ + n0 + tx];
    __syncthreads();
#pragma unroll
    for (int r = 0; r < 32; r += 8) {
        float v = t[tx][ty + r];
        bf16 h, l; split1(v, h, l);
        const size_t o = pk_off(n0 + ty + r, k0 + tx, D_ / 16);
        Oh[o] = h; Ol[o] = l;
    }
}

// ---------------------------------------------------------------------------
// GEMM 1: QKV projection. Q,K written packed row-major; V written as packed
// V^T DIRECTLY (transpose fused via smem staging in the dead pipeline smem).
// ---------------------------------------------------------------------------
__global__ __launch_bounds__(NTHREADS, 2) void gemm_proj_kernel(
    const float* __restrict__ bqp, const float* __restrict__ bkp,
    const float* __restrict__ bvp) {
    const int z = blockIdx.z;
    const float* bias = z == 0 ? bqp : z == 1 ? bkp : bvp;
    const int bm = blockIdx.y * 128, bn = blockIdx.x * 128;

    float acc[4][8][4] = {};
    gemm_core(g_xh, g_xl, g_Wth[z], g_Wtl[z],
              blockIdx.y, blockIdx.x, D_ / BK, D_ / 16, D_ / 16, acc);

    const int tid = threadIdx.x;
    const int lane = tid & 31, warp = tid >> 5;
    const int wm = (warp >> 1) * 64, wn = (warp & 1) * 64;
    const int g = lane >> 2, t = lane & 3;

    if (z < 2) {
        bf16* Ch = z == 0 ? g_Qh : g_Kh;
        bf16* Cl = z == 0 ? g_Ql : g_Kl;
#pragma unroll
        for (int i = 0; i < 4; i++)
#pragma unroll
            for (int j = 0; j < 8; j++) {
                const int col = bn + wn + 8 * j + 2 * t;
                const float b0 = bias[col], b1 = bias[col + 1];
#pragma unroll
                for (int h2 = 0; h2 < 2; h2++) {
                    const int r0 = bm + wm + 16 * i + g + 8 * h2;
                    bf16 h0, l0, h1, l1;
                    split1(acc[i][j][2 * h2 + 0] + b0, h0, l0);
                    split1(acc[i][j][2 * h2 + 1] + b1, h1, l1);
                    const size_t o = pk_off(r0, col, D_ / 16);
                    *(__nv_bfloat162*)(Ch + o) = __halves2bfloat162(h0, h1);
                    *(__nv_bfloat162*)(Cl + o) = __halves2bfloat162(l0, l1);
                }
            }
    } else {
        // V: stage transposed tile in smem (dead after mainloop), then emit
        // packed V^T with 16B stores. sT[c][token], padded stride TSTRIDE.
        extern __shared__ char dsm[];
        bf16* sTh = (bf16*)dsm;                            // 128*136*2 = 34816 B
        bf16* sTl = (bf16*)(dsm + 128 * TSTRIDE * 2);
        __syncthreads();                                    // mainloop smem dead
#pragma unroll
        for (int i = 0; i < 4; i++)
#pragma unroll
            for (int j = 0; j < 8; j++) {
                const int cl = wn + 8 * j + 2 * t;          // local col (d)
                const float b0 = bias[bn + cl], b1 = bias[bn + cl + 1];
#pragma unroll
                for (int h2 = 0; h2 < 2; h2++) {
                    const int rl = wm + 16 * i + g + 8 * h2;  // local token
                    bf16 h0, l0, h1, l1;
                    split1(acc[i][j][2 * h2 + 0] + b0, h0, l0);
                    split1(acc[i][j][2 * h2 + 1] + b1, h1, l1);
                    sTh[cl * TSTRIDE + rl] = h0;
                    sTh[(cl + 1) * TSTRIDE + rl] = h1;
                    sTl[cl * TSTRIDE + rl] = l0;
                    sTl[(cl + 1) * TSTRIDE + rl] = l1;
                }
            }
        __syncthreads();
        const int bb = bm >> 11;                // batch
        const int tk0 = bm & 2047;              // token base within batch
        const int cl2 = tid;                    // one d-column per thread
        const int vrow = bb * D_ + bn + cl2;    // V^T packed row
#pragma unroll
        for (int q = 0; q < 16; q++) {
            const size_t o = pk_off(vrow, tk0 + q * 8, S_ / 16);
            *(uint4*)(g_Vth + o) = *(uint4*)(sTh + cl2 * TSTRIDE + q * 8);
            *(uint4*)(g_Vtl + o) = *(uint4*)(sTl + cl2 * TSTRIDE + q * 8);
        }
    }
}

// ---------------------------------------------------------------------------
// GEMM 2: scores = (Q @ K^T) * scale  (fp32 plain out)
// ---------------------------------------------------------------------------
__global__ __launch_bounds__(NTHREADS, 2) void gemm_scores_kernel() {
    const int b = blockIdx.z;
    const int bm = blockIdx.y * 128, bn = blockIdx.x * 128;

    float acc[4][8][4] = {};
    gemm_core(g_Qh, g_Ql, g_Kh, g_Kl,
              b * 16 + blockIdx.y, b * 16 + blockIdx.x,
              D_ / BK, D_ / 16, D_ / 16, acc);

    float* C = g_S + (size_t)b * S_ * S_;
    const int lane = threadIdx.x & 31, warp = threadIdx.x >> 5;
    const int wm = (warp >> 1) * 64, wn = (warp & 1) * 64;
    const int g = lane >> 2, t = lane & 3;
    const float sc = 0.03125f;
#pragma unroll
    for (int i = 0; i < 4; i++)
#pragma unroll
        for (int j = 0; j < 8; j++) {
            const int col = bn + wn + 8 * j + 2 * t;
            const int r0 = bm + wm + 16 * i + g;
            *(float2*)(C + (size_t)r0 * S_ + col) =
                make_float2(acc[i][j][0] * sc, acc[i][j][1] * sc);
            *(float2*)(C + (size_t)(r0 + 8) * S_ + col) =
                make_float2(acc[i][j][2] * sc, acc[i][j][3] * sc);
        }
}

// ---------------------------------------------------------------------------
// Softmax: fp32 scores -> packed attn bf16 hi/lo (vectorized, 2 barriers)
// ---------------------------------------------------------------------------
__global__ __launch_bounds__(256) void softmax_kernel() {
    const int row = blockIdx.x;
    const float* p = g_S + (size_t)row * S_;
    const int tid = threadIdx.x;
    const int lane = tid & 31, warp = tid >> 5;
    const int k0 = tid * 8;

    __shared__ float red[16];

    float4 a = *(const float4*)(p + k0);
    float4 b = *(const float4*)(p + k0 + 4);
    float v[8] = {a.x, a.y, a.z, a.w, b.x, b.y, b.z, b.w};

    float m = v[0];
#pragma unroll
    for (int i = 1; i < 8; i++) m = fmaxf(m, v[i]);
#pragma unroll
    for (int off = 16; off > 0; off >>= 1)
        m = fmaxf(m, __shfl_xor_sync(0xFFFFFFFFu, m, off));
    if (lane == 0) red[warp] = m;
    __syncthreads();
    m = red[0];
#pragma unroll
    for (int w = 1; w < 8; w++) m = fmaxf(m, red[w]);

    float sum = 0.f;
#pragma unroll
    for (int i = 0; i < 8; i++) {
        v[i] = __expf(v[i] - m);
        sum += v[i];
    }
#pragma unroll
    for (int off = 16; off > 0; off >>= 1)
        sum += __shfl_xor_sync(0xFFFFFFFFu, sum, off);
    if (lane == 0) red[8 + warp] = sum;
    __syncthreads();
    float tot = red[8];
#pragma unroll
    for (int w = 1; w < 8; w++) tot += red[8 + w];
    const float inv = 1.0f / tot;

    uint32_t hw[4], lw[4];
#pragma unroll
    for (int q = 0; q < 4; q++) {
        bf16 h0, l0, h1, l1;
        split1(v[2 * q] * inv, h0, l0);
        split1(v[2 * q + 1] * inv, h1, l1);
        hw[q] = pack2(h0, h1);
        lw[q] = pack2(l0, l1);
    }
    const size_t o = pk_off(row, k0, S_ / 16);
    *(uint4*)(g_Ph + o) = make_uint4(hw[0], hw[1], hw[2], hw[3]);
    *(uint4*)(g_Pl + o) = make_uint4(lw[0], lw[1], lw[2], lw[3]);
}

// ---------------------------------------------------------------------------
// GEMM 3: out = attn @ V  (fp32 plain out)
// ---------------------------------------------------------------------------
__global__ __launch_bounds__(NTHREADS, 2) void gemm_av_kernel(float* __restrict__ out) {
    const int b = blockIdx.z;
    const int bm = blockIdx.y * 128, bn = blockIdx.x * 128;

    float acc[4][8][4] = {};
    gemm_core(g_Ph, g_Pl, g_Vth, g_Vtl,
              b * 16 + blockIdx.y, b * 8 + blockIdx.x,
              S_ / BK, S_ / 16, S_ / 16, acc);

    float* C = out + (size_t)b * S_ * D_;
    const int lane = threadIdx.x & 31, warp = threadIdx.x >> 5;
    const int wm = (warp >> 1) * 64, wn = (warp & 1) * 64;
    const int g = lane >> 2, t = lane & 3;
#pragma unroll
    for (int i = 0; i < 4; i++)
#pragma unroll
        for (int j = 0; j < 8; j++) {
            const int col = bn + wn + 8 * j + 2 * t;
            const int r0 = bm + wm + 16 * i + g;
            *(float2*)(C + (size_t)r0 * D_ + col) =
                make_float2(acc[i][j][0], acc[i][j][1]);
            *(float2*)(C + (size_t)(r0 + 8) * D_ + col) =
                make_float2(acc[i][j][2], acc[i][j][3]);
        }
}

// ---------------------------------------------------------------------------
// Launch (single stream; transpose_V eliminated — fused into proj)
// ---------------------------------------------------------------------------
extern "C" void kernel_launch(void* const* d_in, const int* in_sizes, int n_in,
                              void* d_out, int out_size) {
    const float* x  = (const float*)d_in[0];
    const float* Wq = (const float*)d_in[1];
    const float* bq = (const float*)d_in[2];
    const float* Wk = (const float*)d_in[3];
    const float* bk = (const float*)d_in[4];
    const float* Wv = (const float*)d_in[5];
    const float* bv = (const float*)d_in[6];
    float* out = (float*)d_out;

    cudaFuncSetAttribute(gemm_proj_kernel,
                         cudaFuncAttributeMaxDynamicSharedMemorySize, SMEM_DYN);
    cudaFuncSetAttribute(gemm_scores_kernel,
                         cudaFuncAttributeMaxDynamicSharedMemorySize, SMEM_DYN);
    cudaFuncSetAttribute(gemm_av_kernel,
                         cudaFuncAttributeMaxDynamicSharedMemorySize, SMEM_DYN);

    convert_x_kernel<<<(MS * D_) / 2048, 256>>>(x);
    convert_Wt_kernel<<<dim3(32, 32, 3), dim3(32, 8)>>>(Wq, Wk, Wv);

    gemm_proj_kernel<<<dim3(D_ / 128, MS / 128, 3), NTHREADS, SMEM_DYN>>>(bq, bk, bv);

    gemm_scores_kernel<<<dim3(S_ / 128, S_ / 128, B_), NTHREADS, SMEM_DYN>>>();

    softmax_kernel<<<B_ * S_, 256>>>();

    gemm_av_kernel<<<dim3(D_ / 128, S_ / 128, B_), NTHREADS, SMEM_DYN>>>(out);
}